// round 1
// baseline (speedup 1.0000x reference)
#include <cuda_runtime.h>
#include <cuda_bf16.h>

// Sparsemax over last dim: rows of N=512 fp32.
// One row per 128-thread block; 4 elems/thread in a float4 (registers).
// Michelot fixed-point iteration for the simplex-projection threshold tau:
//   tau_{t+1} = (sum_{z_i > tau_t} z_i - 1) / |{z_i > tau_t}|
// Monotone (support shrinks) and finite; at convergence tau is EXACT,
// identical to the sort-based reference up to fp32 rounding.

#define N 512
#define THREADS 128

__global__ __launch_bounds__(THREADS)
void sparsemax_kernel(const float* __restrict__ in, float* __restrict__ out) {
    const size_t row = blockIdx.x;
    const float4* __restrict__ rp =
        reinterpret_cast<const float4*>(in) + row * (N / 4);

    float4 v = rp[threadIdx.x];

    __shared__ float sh_s[4];   // per-warp partial sums
    __shared__ float sh_c[4];   // per-warp partial counts

    const int lane = threadIdx.x & 31;
    const int warp = threadIdx.x >> 5;   // 0..3

    // ---- row max (for numerical stability; matches reference shift) ----
    float m = fmaxf(fmaxf(v.x, v.y), fmaxf(v.z, v.w));
    #pragma unroll
    for (int o = 16; o; o >>= 1)
        m = fmaxf(m, __shfl_xor_sync(0xffffffffu, m, o));
    if (lane == 0) sh_s[warp] = m;
    __syncthreads();
    m = fmaxf(fmaxf(sh_s[0], sh_s[1]), fmaxf(sh_s[2], sh_s[3]));

    v.x -= m; v.y -= m; v.z -= m; v.w -= m;

    // ---- initial tau over the full set: tau = (sum(z) - 1) / N ----
    float s = v.x + v.y + v.z + v.w;
    #pragma unroll
    for (int o = 16; o; o >>= 1)
        s += __shfl_xor_sync(0xffffffffu, s, o);
    __syncthreads();                 // everyone done reading sh_s as max buffer
    if (lane == 0) sh_s[warp] = s;
    __syncthreads();
    float tau = (sh_s[0] + sh_s[1] + sh_s[2] + sh_s[3] - 1.0f) * (1.0f / (float)N);

    // ---- Michelot iteration: shrink support until stable ----
    int k_prev = N;
    #pragma unroll 1
    for (int it = 0; it < 64; ++it) {
        float ps = 0.0f;
        float pc = 0.0f;
        if (v.x > tau) { ps += v.x; pc += 1.0f; }
        if (v.y > tau) { ps += v.y; pc += 1.0f; }
        if (v.z > tau) { ps += v.z; pc += 1.0f; }
        if (v.w > tau) { ps += v.w; pc += 1.0f; }

        #pragma unroll
        for (int o = 16; o; o >>= 1) {
            ps += __shfl_xor_sync(0xffffffffu, ps, o);
            pc += __shfl_xor_sync(0xffffffffu, pc, o);
        }
        __syncthreads();             // previous iteration's reads of sh_* done
        if (lane == 0) { sh_s[warp] = ps; sh_c[warp] = pc; }
        __syncthreads();

        float tot = sh_s[0] + sh_s[1] + sh_s[2] + sh_s[3];
        float cnt = sh_c[0] + sh_c[1] + sh_c[2] + sh_c[3];
        int k = (int)cnt;
        // cnt >= 1 always: z_max = 0 and tau <= -1/k < 0, so no div-by-zero.
        tau = (tot - 1.0f) / cnt;
        if (k == k_prev) break;      // support stable -> tau exact (uniform branch)
        k_prev = k;
    }

    // ---- output: max(z - tau, 0) ----
    float4 o4;
    o4.x = fmaxf(v.x - tau, 0.0f);
    o4.y = fmaxf(v.y - tau, 0.0f);
    o4.z = fmaxf(v.z - tau, 0.0f);
    o4.w = fmaxf(v.w - tau, 0.0f);
    reinterpret_cast<float4*>(out)[row * (N / 4) + threadIdx.x] = o4;
}

extern "C" void kernel_launch(void* const* d_in, const int* in_sizes, int n_in,
                              void* d_out, int out_size) {
    const float* in = (const float*)d_in[0];
    float* out = (float*)d_out;
    const int rows = in_sizes[0] / N;   // 64*1024 = 65536
    sparsemax_kernel<<<rows, THREADS>>>(in, out);
}

// round 2
// speedup vs baseline: 2.7648x; 2.7648x over previous
#include <cuda_runtime.h>
#include <cuda_bf16.h>

// Sparsemax over last dim: rows of N=512 fp32.
// ONE WARP per row: 32 lanes x 16 elements, all register-resident.
// Michelot fixed-point iteration for the simplex-projection threshold tau:
//   tau_{t+1} = (sum_{z_i > tau_t} z_i - 1) / |{z_i > tau_t}|
// Support shrinks monotonically; at convergence tau is exact (matches the
// sort-based reference to fp32 rounding).
// All reductions are warp-local: 5 SHFL for the float sum, one REDUX.ADD
// (__reduce_add_sync) for the integer count. No smem, no __syncthreads.

#define N 512
#define ROWS_PER_BLOCK 8
#define THREADS (32 * ROWS_PER_BLOCK)

__global__ __launch_bounds__(THREADS)
void sparsemax_kernel(const float4* __restrict__ in, float4* __restrict__ out) {
    const int lane = threadIdx.x & 31;
    const size_t row = (size_t)blockIdx.x * ROWS_PER_BLOCK + (threadIdx.x >> 5);
    const float4* __restrict__ rp = in + row * (N / 4);

    // 16 elements per lane, coalesced: float4 slots {lane, lane+32, lane+64, lane+96}
    float4 v[4];
    #pragma unroll
    for (int i = 0; i < 4; ++i) v[i] = rp[lane + 32 * i];

    // ---- row max (numerical-stability shift, matches reference) ----
    float m = -3.4e38f;
    #pragma unroll
    for (int i = 0; i < 4; ++i)
        m = fmaxf(m, fmaxf(fmaxf(v[i].x, v[i].y), fmaxf(v[i].z, v[i].w)));
    #pragma unroll
    for (int o = 16; o; o >>= 1)
        m = fmaxf(m, __shfl_xor_sync(0xffffffffu, m, o));

    // ---- shift + full-set sum for initial tau = (sum(z) - 1) / N ----
    float s = 0.0f;
    #pragma unroll
    for (int i = 0; i < 4; ++i) {
        v[i].x -= m; v[i].y -= m; v[i].z -= m; v[i].w -= m;
        s += (v[i].x + v[i].y) + (v[i].z + v[i].w);
    }
    #pragma unroll
    for (int o = 16; o; o >>= 1)
        s += __shfl_xor_sync(0xffffffffu, s, o);

    float tau = (s - 1.0f) * (1.0f / (float)N);

    // ---- Michelot iteration: shrink support until stable ----
    int k_prev = N;
    #pragma unroll 1
    for (int it = 0; it < 64; ++it) {
        float ps = 0.0f;
        int   pc = 0;
        #pragma unroll
        for (int i = 0; i < 4; ++i) {
            if (v[i].x > tau) { ps += v[i].x; ++pc; }
            if (v[i].y > tau) { ps += v[i].y; ++pc; }
            if (v[i].z > tau) { ps += v[i].z; ++pc; }
            if (v[i].w > tau) { ps += v[i].w; ++pc; }
        }
        #pragma unroll
        for (int o = 16; o; o >>= 1)
            ps += __shfl_xor_sync(0xffffffffu, ps, o);
        pc = __reduce_add_sync(0xffffffffu, pc);   // REDUX.ADD, 1 instr

        // pc >= 1 always (z_max = 0, tau < 0), so no div-by-zero.
        tau = (ps - 1.0f) / (float)pc;
        if (pc == k_prev) break;                   // uniform per-warp branch
        k_prev = pc;
    }

    // ---- output: max(z - tau, 0) ----
    float4* __restrict__ wp = out + row * (N / 4);
    #pragma unroll
    for (int i = 0; i < 4; ++i) {
        float4 o4;
        o4.x = fmaxf(v[i].x - tau, 0.0f);
        o4.y = fmaxf(v[i].y - tau, 0.0f);
        o4.z = fmaxf(v[i].z - tau, 0.0f);
        o4.w = fmaxf(v[i].w - tau, 0.0f);
        wp[lane + 32 * i] = o4;
    }
}

extern "C" void kernel_launch(void* const* d_in, const int* in_sizes, int n_in,
                              void* d_out, int out_size) {
    const float4* in = (const float4*)d_in[0];
    float4* out = (float4*)d_out;
    const int rows = in_sizes[0] / N;                 // 65536
    sparsemax_kernel<<<rows / ROWS_PER_BLOCK, THREADS>>>(in, out);
}

// round 3
// speedup vs baseline: 3.4263x; 1.2392x over previous
#include <cuda_runtime.h>
#include <cuda_bf16.h>

// Sparsemax over last dim: rows of N=512 fp32. One warp per row,
// 32 lanes x 16 elements register-resident.
//
// Michelot fixed-point in x-space with a warm start:
//   theta_0 = max(x) - 1           (provably <= theta* since g(max-1) >= 1)
//   S = {x > theta},  theta' = (sum_S x - 1) / |S|
// theta is monotone non-decreasing, support shrinks; when |S| repeats the
// support is unchanged and theta is exact (matches sorted reference).
// Output: max(x - theta, 0)  ==  max(z - tau, 0) with z = x - max, tau = theta - max.
//
// Warm start means ~2-3 iterations instead of ~6 (support starts at ~6 elems
// for Gaussian data instead of ~256).

#define N 512
#define ROWS_PER_BLOCK 8
#define THREADS (32 * ROWS_PER_BLOCK)

// monotone float<->uint mapping for integer max-reduction (no NaNs in data)
__device__ __forceinline__ unsigned f2mono(float f) {
    unsigned u = __float_as_uint(f);
    return u ^ ((unsigned)((int)u >> 31) | 0x80000000u);
}
__device__ __forceinline__ float mono2f(unsigned k) {
    unsigned u = k ^ ((unsigned)((int)(~k) >> 31) | 0x80000000u);
    return __uint_as_float(u);
}

__global__ __launch_bounds__(THREADS)
void sparsemax_kernel(const float4* __restrict__ in, float4* __restrict__ out) {
    const int lane = threadIdx.x & 31;
    const size_t row = (size_t)blockIdx.x * ROWS_PER_BLOCK + (threadIdx.x >> 5);
    const float4* __restrict__ rp = in + row * (N / 4);

    // 16 elements per lane, coalesced: float4 slots {lane, lane+32, lane+64, lane+96}
    float4 v[4];
    #pragma unroll
    for (int i = 0; i < 4; ++i) v[i] = __ldcs(&rp[lane + 32 * i]);

    // ---- row max via single REDUX.MAX (monotone uint encoding) ----
    float m = fmaxf(fmaxf(v[0].x, v[0].y), fmaxf(v[0].z, v[0].w));
    #pragma unroll
    for (int i = 1; i < 4; ++i)
        m = fmaxf(m, fmaxf(fmaxf(v[i].x, v[i].y), fmaxf(v[i].z, v[i].w)));
    m = mono2f(__reduce_max_sync(0xffffffffu, f2mono(m)));

    // ---- Michelot from warm start theta0 = max - 1 ----
    float theta = m - 1.0f;
    int k_prev = -1;
    #pragma unroll 1
    for (int it = 0; it < 48; ++it) {
        float ps = 0.0f;
        int   pc = 0;
        #pragma unroll
        for (int i = 0; i < 4; ++i) {
            if (v[i].x > theta) { ps += v[i].x; ++pc; }
            if (v[i].y > theta) { ps += v[i].y; ++pc; }
            if (v[i].z > theta) { ps += v[i].z; ++pc; }
            if (v[i].w > theta) { ps += v[i].w; ++pc; }
        }
        #pragma unroll
        for (int o = 16; o; o >>= 1)
            ps += __shfl_xor_sync(0xffffffffu, ps, o);
        pc = __reduce_add_sync(0xffffffffu, pc);    // REDUX.ADD

        // pc >= 1 always: x_max = m > m-1 = theta0, and theta <= theta* < m.
        theta = __fdividef(ps - 1.0f, (float)pc);
        if (pc == k_prev) break;                    // support stable -> theta exact
        k_prev = pc;
    }

    // ---- output: max(x - theta, 0) ----
    float4* __restrict__ wp = out + row * (N / 4);
    #pragma unroll
    for (int i = 0; i < 4; ++i) {
        float4 o4;
        o4.x = fmaxf(v[i].x - theta, 0.0f);
        o4.y = fmaxf(v[i].y - theta, 0.0f);
        o4.z = fmaxf(v[i].z - theta, 0.0f);
        o4.w = fmaxf(v[i].w - theta, 0.0f);
        wp[lane + 32 * i] = o4;
    }
}

extern "C" void kernel_launch(void* const* d_in, const int* in_sizes, int n_in,
                              void* d_out, int out_size) {
    const float4* in = (const float4*)d_in[0];
    float4* out = (float4*)d_out;
    const int rows = in_sizes[0] / N;                 // 65536
    sparsemax_kernel<<<rows / ROWS_PER_BLOCK, THREADS>>>(in, out);
}